// round 10
// baseline (speedup 1.0000x reference)
#include <cuda_runtime.h>
#include <cuda_bf16.h>
#include <math.h>
#include <stdint.h>

// ---------------------------------------------------------------------------
// SimpleSelfAttention B=4,S=2048,D=1024 fp32.
// GEMMs via warp-level mma.sync bf16 (HMMA) with fp32 split:
//   C = A @ B^T computed as Ah*Bh + Ah*Bl + Al*Bh   (error ~2^-18)
// NOTE: tcgen05/TMEM PTX is rejected by this harness's compute_103 lowering,
// so tensor cores are driven through baseline mma.sync.
// ---------------------------------------------------------------------------

#define BM 128
#define BN 128
#define BK 32
#define STAGE_BYTES 32768   // Ah(8K) Al(8K) Bh(8K) Bl(8K)
#define AH_OFF 0
#define AL_OFF 8192
#define BH_OFF 16384
#define BL_OFF 24576
#define SMEM_TOTAL (2 * STAGE_BYTES)

// scratch
__device__ float g_Q[4 * 2048 * 1024];
__device__ float g_K[4 * 2048 * 1024];
__device__ float g_V[4 * 2048 * 1024];
__device__ float g_Vt[4 * 2048 * 1024];
__device__ float g_S[4 * 2048 * 2048];

__device__ __forceinline__ uint32_t smem_u32(const void* p) {
    uint32_t a;
    asm("{ .reg .u64 t; cvta.to.shared.u64 t, %1; cvt.u32.u64 %0, t; }"
        : "=r"(a) : "l"(p));
    return a;
}

// Swizzled byte offset for (row, 16B-chunk) in a [rows][32 bf16] tile (64B rows).
// Guarantees conflict-free ldmatrix phases (8 rows hit 8 distinct 16B groups).
__device__ __forceinline__ uint32_t swz(int r, int c) {
    return (uint32_t)(r * 64 + ((c ^ ((r >> 1) & 3)) << 4));
}

__device__ __forceinline__ void ldsm4(uint32_t* r, uint32_t a) {
    asm volatile(
        "ldmatrix.sync.aligned.m8n8.x4.shared.b16 {%0,%1,%2,%3}, [%4];"
        : "=r"(r[0]), "=r"(r[1]), "=r"(r[2]), "=r"(r[3]) : "r"(a));
}
__device__ __forceinline__ void ldsm2(uint32_t* r, uint32_t a) {
    asm volatile(
        "ldmatrix.sync.aligned.m8n8.x2.shared.b16 {%0,%1}, [%2];"
        : "=r"(r[0]), "=r"(r[1]) : "r"(a));
}
__device__ __forceinline__ void mma_bf16(float* c, const uint32_t* a,
                                         const uint32_t* b) {
    asm volatile(
        "mma.sync.aligned.m16n8k16.row.col.f32.bf16.bf16.f32 "
        "{%0,%1,%2,%3}, {%4,%5,%6,%7}, {%8,%9}, {%0,%1,%2,%3};"
        : "+f"(c[0]), "+f"(c[1]), "+f"(c[2]), "+f"(c[3])
        : "r"(a[0]), "r"(a[1]), "r"(a[2]), "r"(a[3]), "r"(b[0]), "r"(b[1]));
}

__device__ __forceinline__ void split_pair(float a, float b, uint32_t& h,
                                           uint32_t& l) {
    __nv_bfloat162 hv = __floats2bfloat162_rn(a, b);
    float ha = __bfloat162float(hv.x), hb = __bfloat162float(hv.y);
    __nv_bfloat162 lv = __floats2bfloat162_rn(a - ha, b - hb);
    h = *reinterpret_cast<uint32_t*>(&hv);
    l = *reinterpret_cast<uint32_t*>(&lv);
}
__device__ __forceinline__ void split8(const float4& v0, const float4& v1,
                                       uint4& h, uint4& l) {
    split_pair(v0.x, v0.y, h.x, l.x);
    split_pair(v0.z, v0.w, h.y, l.y);
    split_pair(v1.x, v1.y, h.z, l.z);
    split_pair(v1.z, v1.w, h.w, l.w);
}

// ---------------- HMMA NT GEMM: C = scale*(A @ B^T) [+bias] [+mask] --------
__global__ __launch_bounds__(256, 1) void gemm_mma(
    const float* __restrict__ Ag, const float* __restrict__ Bg,
    float* __restrict__ Cg, int M, int N, int Kdim,
    long long sAz, long long sBz, long long sCz,
    const float* __restrict__ bias, const float* __restrict__ mask,
    float scale) {
    extern __shared__ char sm[];
    const uint32_t smb = smem_u32(sm);
    const int tid = threadIdx.x;
    const int wid = tid >> 5;
    const int lane = tid & 31;

    const float* A = Ag + (long long)blockIdx.z * sAz;
    const float* B = Bg + (long long)blockIdx.z * sBz;
    float* C = Cg + (long long)blockIdx.z * sCz;
    const int m0 = blockIdx.y * BM;
    const int n0 = blockIdx.x * BN;

    const float* arow = A + (size_t)m0 * Kdim;
    const float* brow = B + (size_t)n0 * Kdim;

    // per-thread gmem->smem mapping: 2 (row,chunk) pairs per tile
    const int r0g = tid >> 2;            // 0..63
    const int c0g = tid & 3;             // chunk 0..3 (8 floats)
    const int NC = Kdim / BK;

    const int wm = wid & 1;              // m half
    const int wn = wid >> 1;             // n quarter
    const int m_base = wm * 64;
    const int n_base = wn * 32;

    float acc[4][4][4];
#pragma unroll
    for (int i = 0; i < 4; i++)
#pragma unroll
        for (int j = 0; j < 4; j++)
#pragma unroll
            for (int k = 0; k < 4; k++) acc[i][j][k] = 0.f;

    // ldmatrix per-lane addressing pieces (constant)
    const int arow_in = lane & 15;
    const int asel = lane >> 4;          // 0/1 -> k chunk within kchunk
    const int brow_in = lane & 7;
    const int bsel = (lane >> 3) & 1;

    // ---- prologue: stage 0 ----
    {
        char* st = sm;
#pragma unroll
        for (int t = 0; t < 2; t++) {
            int r = r0g + t * 64;
            const float* p = arow + (size_t)r * Kdim + c0g * 8;
            float4 v0 = *reinterpret_cast<const float4*>(p);
            float4 v1 = *reinterpret_cast<const float4*>(p + 4);
            uint4 h, l;
            split8(v0, v1, h, l);
            uint32_t off = swz(r, c0g);
            *reinterpret_cast<uint4*>(st + AH_OFF + off) = h;
            *reinterpret_cast<uint4*>(st + AL_OFF + off) = l;
            const float* q = brow + (size_t)r * Kdim + c0g * 8;
            float4 w0 = *reinterpret_cast<const float4*>(q);
            float4 w1 = *reinterpret_cast<const float4*>(q + 4);
            split8(w0, w1, h, l);
            *reinterpret_cast<uint4*>(st + BH_OFF + off) = h;
            *reinterpret_cast<uint4*>(st + BL_OFF + off) = l;
        }
    }
    __syncthreads();

    for (int c = 0; c < NC; c++) {
        const uint32_t sbase = smb + (uint32_t)(c & 1) * STAGE_BYTES;
        char* nxt = sm + ((c + 1) & 1) * STAGE_BYTES;

        // prefetch next stage gmem -> regs
        float4 pa[2][2], pb[2][2];
        if (c + 1 < NC) {
            const float* ac = arow + (size_t)(c + 1) * BK;
            const float* bc = brow + (size_t)(c + 1) * BK;
#pragma unroll
            for (int t = 0; t < 2; t++) {
                int r = r0g + t * 64;
                const float* p = ac + (size_t)r * Kdim + c0g * 8;
                pa[t][0] = *reinterpret_cast<const float4*>(p);
                pa[t][1] = *reinterpret_cast<const float4*>(p + 4);
                const float* q = bc + (size_t)r * Kdim + c0g * 8;
                pb[t][0] = *reinterpret_cast<const float4*>(q);
                pb[t][1] = *reinterpret_cast<const float4*>(q + 4);
            }
        }

        // ---- compute k-chunk 0 ----
#pragma unroll
        for (int kc2 = 0; kc2 < 2; kc2++) {
            if (kc2 == 1 && c + 1 < NC) {
                // store next stage between the two k-chunks
#pragma unroll
                for (int t = 0; t < 2; t++) {
                    int r = r0g + t * 64;
                    uint4 h, l;
                    split8(pa[t][0], pa[t][1], h, l);
                    uint32_t off = swz(r, c0g);
                    *reinterpret_cast<uint4*>(nxt + AH_OFF + off) = h;
                    *reinterpret_cast<uint4*>(nxt + AL_OFF + off) = l;
                    split8(pb[t][0], pb[t][1], h, l);
                    *reinterpret_cast<uint4*>(nxt + BH_OFF + off) = h;
                    *reinterpret_cast<uint4*>(nxt + BL_OFF + off) = l;
                }
            }
            uint32_t ah[4][4], al[4][4], bh[4][2], bl[4][2];
            int achunk = kc2 * 2 + asel;
#pragma unroll
            for (int mi = 0; mi < 4; mi++) {
                uint32_t off = swz(m_base + mi * 16 + arow_in, achunk);
                ldsm4(ah[mi], sbase + AH_OFF + off);
                ldsm4(al[mi], sbase + AL_OFF + off);
            }
            int bchunk = kc2 * 2 + bsel;
#pragma unroll
            for (int ni = 0; ni < 4; ni++) {
                uint32_t off = swz(n_base + ni * 8 + brow_in, bchunk);
                ldsm2(bh[ni], sbase + BH_OFF + off);
                ldsm2(bl[ni], sbase + BL_OFF + off);
            }
#pragma unroll
            for (int mi = 0; mi < 4; mi++)
#pragma unroll
                for (int ni = 0; ni < 4; ni++) {
                    mma_bf16(acc[mi][ni], ah[mi], bh[ni]);
                    mma_bf16(acc[mi][ni], ah[mi], bl[ni]);
                    mma_bf16(acc[mi][ni], al[mi], bh[ni]);
                }
        }
        __syncthreads();
    }

    // ---- epilogue ----
    const int mrow0 = m0 + m_base;
    const int ncol0 = n0 + n_base;
#pragma unroll
    for (int mi = 0; mi < 4; mi++) {
#pragma unroll
        for (int half = 0; half < 2; half++) {
            int row = mrow0 + mi * 16 + (lane >> 2) + half * 8;
            float* crow = C + (size_t)row * N;
            const float* mrow = mask ? mask + (size_t)row * N : nullptr;
#pragma unroll
            for (int ni = 0; ni < 4; ni++) {
                int col = ncol0 + ni * 8 + (lane & 3) * 2;
                float v0 = acc[mi][ni][half * 2 + 0] * scale;
                float v1 = acc[mi][ni][half * 2 + 1] * scale;
                if (bias) {
                    v0 += bias[col];
                    v1 += bias[col + 1];
                }
                if (mrow) {
                    v0 += mrow[col];
                    v1 += mrow[col + 1];
                }
                *reinterpret_cast<float2*>(crow + col) = make_float2(v0, v1);
            }
        }
    }
}

// ---------------- batched transpose: V[b][2048][1024] -> Vt[b][1024][2048] --
__global__ __launch_bounds__(256) void transpose_kernel(
    const float* __restrict__ src, float* __restrict__ dst) {
    __shared__ float t[32][33];
    const float* s = src + (size_t)blockIdx.z * 2048 * 1024;
    float* d = dst + (size_t)blockIdx.z * 2048 * 1024;
    int c0 = blockIdx.x * 32;
    int r0 = blockIdx.y * 32;
    int tx = threadIdx.x & 31, ty = threadIdx.x >> 5;
#pragma unroll
    for (int i = 0; i < 32; i += 8)
        t[ty + i][tx] = s[(size_t)(r0 + ty + i) * 1024 + c0 + tx];
    __syncthreads();
#pragma unroll
    for (int i = 0; i < 32; i += 8)
        d[(size_t)(c0 + ty + i) * 2048 + r0 + tx] = t[tx][ty + i];
}

// ---------------- row softmax over 2048 cols ----------------
__global__ __launch_bounds__(256) void softmax_kernel(float* __restrict__ S,
                                                      int n) {
    size_t row = blockIdx.x;
    float* p = S + row * (size_t)n;
    int tid = threadIdx.x;
    int lane = tid & 31, warp = tid >> 5;

    float4 v0 = reinterpret_cast<float4*>(p)[tid];
    float4 v1 = reinterpret_cast<float4*>(p)[tid + 256];
    float v[8] = {v0.x, v0.y, v0.z, v0.w, v1.x, v1.y, v1.z, v1.w};
    __shared__ float red[8];

    float m = v[0];
#pragma unroll
    for (int j = 1; j < 8; j++) m = fmaxf(m, v[j]);
#pragma unroll
    for (int o = 16; o; o >>= 1) m = fmaxf(m, __shfl_xor_sync(0xffffffffu, m, o));
    if (lane == 0) red[warp] = m;
    __syncthreads();
    float mall = red[0];
#pragma unroll
    for (int i = 1; i < 8; i++) mall = fmaxf(mall, red[i]);
    __syncthreads();

    float s = 0.f;
#pragma unroll
    for (int j = 0; j < 8; j++) {
        v[j] = expf(v[j] - mall);
        s += v[j];
    }
#pragma unroll
    for (int o = 16; o; o >>= 1) s += __shfl_xor_sync(0xffffffffu, s, o);
    if (lane == 0) red[warp] = s;
    __syncthreads();
    float stot = 0.f;
#pragma unroll
    for (int i = 0; i < 8; i++) stot += red[i];
    float inv = 1.0f / stot;

    reinterpret_cast<float4*>(p)[tid] =
        make_float4(v[0] * inv, v[1] * inv, v[2] * inv, v[3] * inv);
    reinterpret_cast<float4*>(p)[tid + 256] =
        make_float4(v[4] * inv, v[5] * inv, v[6] * inv, v[7] * inv);
}

extern "C" void kernel_launch(void* const* d_in, const int* in_sizes, int n_in,
                              void* d_out, int out_size) {
    const float* x    = (const float*)d_in[0];
    const float* mask = (const float*)d_in[1];
    const float* w_q  = (const float*)d_in[2];
    const float* b_q  = (const float*)d_in[3];
    const float* w_k  = (const float*)d_in[4];
    const float* b_k  = (const float*)d_in[5];
    const float* w_v  = (const float*)d_in[6];
    const float* b_v  = (const float*)d_in[7];
    float* out = (float*)d_out;

    float *Qp, *Kp, *Vp, *Vtp, *Sp;
    cudaGetSymbolAddress((void**)&Qp, g_Q);
    cudaGetSymbolAddress((void**)&Kp, g_K);
    cudaGetSymbolAddress((void**)&Vp, g_V);
    cudaGetSymbolAddress((void**)&Vtp, g_Vt);
    cudaGetSymbolAddress((void**)&Sp, g_S);

    cudaFuncSetAttribute(gemm_mma, cudaFuncAttributeMaxDynamicSharedMemorySize,
                         SMEM_TOTAL);

    const int Bb = 4, Ss = 2048, Dd = 1024;
    const int M_qkv = Bb * Ss;  // 8192
    const float inv_sqrt_d = 1.0f / 32.0f;
    dim3 blk(256);

    // QKV projections: [8192,1024] = x @ W^T + b
    dim3 g_qkv(Dd / BN, M_qkv / BM, 1);
    gemm_mma<<<g_qkv, blk, SMEM_TOTAL>>>(x, w_q, Qp, M_qkv, Dd, Dd, 0, 0, 0,
                                         b_q, nullptr, 1.0f);
    gemm_mma<<<g_qkv, blk, SMEM_TOTAL>>>(x, w_k, Kp, M_qkv, Dd, Dd, 0, 0, 0,
                                         b_k, nullptr, 1.0f);
    gemm_mma<<<g_qkv, blk, SMEM_TOTAL>>>(x, w_v, Vp, M_qkv, Dd, Dd, 0, 0, 0,
                                         b_v, nullptr, 1.0f);

    // Vt[b] = V[b]^T  (so attn@V becomes NT)
    dim3 g_tr(Dd / 32, Ss / 32, Bb);
    transpose_kernel<<<g_tr, blk>>>(Vp, Vtp);

    // scores[b] = Q[b] @ K[b]^T / 32 + mask
    dim3 g_sc(Ss / BN, Ss / BM, Bb);
    gemm_mma<<<g_sc, blk, SMEM_TOTAL>>>(Qp, Kp, Sp, Ss, Ss, Dd,
                                        (long long)Ss * Dd, (long long)Ss * Dd,
                                        (long long)Ss * Ss, nullptr, mask,
                                        inv_sqrt_d);

    // softmax rows
    softmax_kernel<<<Bb * Ss, blk>>>(Sp, Ss);

    // out[b] = attn[b] @ Vt[b]^T
    dim3 g_av(Dd / BN, Ss / BM, Bb);
    gemm_mma<<<g_av, blk, SMEM_TOTAL>>>(Sp, Vtp, out, Ss, Dd, Ss,
                                        (long long)Ss * Ss, (long long)Ss * Dd,
                                        (long long)Ss * Dd, nullptr, nullptr,
                                        1.0f);
}

// round 11
// speedup vs baseline: 1.0016x; 1.0016x over previous
#include <cuda_runtime.h>
#include <cuda_bf16.h>
#include <math.h>
#include <stdint.h>

// ---------------------------------------------------------------------------
// SimpleSelfAttention B=4,S=2048,D=1024 fp32.
// GEMMs via warp-level mma.sync bf16 (HMMA) with fp32 split:
//   C = A @ B^T computed as Ah*Bh + Ah*Bl + Al*Bh   (error ~2^-18)
// NOTE: tcgen05/TMEM PTX is rejected by this harness's compute_103 lowering,
// so tensor cores are driven through baseline mma.sync.
// ---------------------------------------------------------------------------

#define BM 128
#define BN 128
#define BK 32
#define STAGE_BYTES 32768   // Ah(8K) Al(8K) Bh(8K) Bl(8K)
#define AH_OFF 0
#define AL_OFF 8192
#define BH_OFF 16384
#define BL_OFF 24576
#define SMEM_TOTAL (2 * STAGE_BYTES)

// scratch
__device__ float g_Q[4 * 2048 * 1024];
__device__ float g_K[4 * 2048 * 1024];
__device__ float g_V[4 * 2048 * 1024];
__device__ float g_Vt[4 * 2048 * 1024];
__device__ float g_S[4 * 2048 * 2048];

__device__ __forceinline__ uint32_t smem_u32(const void* p) {
    uint32_t a;
    asm("{ .reg .u64 t; cvta.to.shared.u64 t, %1; cvt.u32.u64 %0, t; }"
        : "=r"(a) : "l"(p));
    return a;
}

// Swizzled byte offset for (row, 16B-chunk) in a [rows][32 bf16] tile (64B rows).
// Guarantees conflict-free ldmatrix phases (8 rows hit 8 distinct 16B groups).
__device__ __forceinline__ uint32_t swz(int r, int c) {
    return (uint32_t)(r * 64 + ((c ^ ((r >> 1) & 3)) << 4));
}

__device__ __forceinline__ void ldsm4(uint32_t* r, uint32_t a) {
    asm volatile(
        "ldmatrix.sync.aligned.m8n8.x4.shared.b16 {%0,%1,%2,%3}, [%4];"
        : "=r"(r[0]), "=r"(r[1]), "=r"(r[2]), "=r"(r[3]) : "r"(a));
}
__device__ __forceinline__ void ldsm2(uint32_t* r, uint32_t a) {
    asm volatile(
        "ldmatrix.sync.aligned.m8n8.x2.shared.b16 {%0,%1}, [%2];"
        : "=r"(r[0]), "=r"(r[1]) : "r"(a));
}
__device__ __forceinline__ void mma_bf16(float* c, const uint32_t* a,
                                         const uint32_t* b) {
    asm volatile(
        "mma.sync.aligned.m16n8k16.row.col.f32.bf16.bf16.f32 "
        "{%0,%1,%2,%3}, {%4,%5,%6,%7}, {%8,%9}, {%0,%1,%2,%3};"
        : "+f"(c[0]), "+f"(c[1]), "+f"(c[2]), "+f"(c[3])
        : "r"(a[0]), "r"(a[1]), "r"(a[2]), "r"(a[3]), "r"(b[0]), "r"(b[1]));
}

__device__ __forceinline__ void split_pair(float a, float b, uint32_t& h,
                                           uint32_t& l) {
    __nv_bfloat162 hv = __floats2bfloat162_rn(a, b);
    float ha = __bfloat162float(hv.x), hb = __bfloat162float(hv.y);
    __nv_bfloat162 lv = __floats2bfloat162_rn(a - ha, b - hb);
    h = *reinterpret_cast<uint32_t*>(&hv);
    l = *reinterpret_cast<uint32_t*>(&lv);
}
__device__ __forceinline__ void split8(const float4& v0, const float4& v1,
                                       uint4& h, uint4& l) {
    split_pair(v0.x, v0.y, h.x, l.x);
    split_pair(v0.z, v0.w, h.y, l.y);
    split_pair(v1.x, v1.y, h.z, l.z);
    split_pair(v1.z, v1.w, h.w, l.w);
}

// ---------------- HMMA NT GEMM: C = scale*(A @ B^T) [+bias] [+mask] --------
__global__ __launch_bounds__(256, 1) void gemm_mma(
    const float* __restrict__ Ag, const float* __restrict__ Bg,
    float* __restrict__ Cg, int M, int N, int Kdim,
    long long sAz, long long sBz, long long sCz,
    const float* __restrict__ bias, const float* __restrict__ mask,
    float scale) {
    extern __shared__ char sm[];
    const uint32_t smb = smem_u32(sm);
    const int tid = threadIdx.x;
    const int wid = tid >> 5;
    const int lane = tid & 31;

    const float* A = Ag + (long long)blockIdx.z * sAz;
    const float* B = Bg + (long long)blockIdx.z * sBz;
    float* C = Cg + (long long)blockIdx.z * sCz;
    const int m0 = blockIdx.y * BM;
    const int n0 = blockIdx.x * BN;

    const float* arow = A + (size_t)m0 * Kdim;
    const float* brow = B + (size_t)n0 * Kdim;

    // per-thread gmem->smem mapping: 2 (row,chunk) pairs per tile
    const int r0g = tid >> 2;            // 0..63
    const int c0g = tid & 3;             // chunk 0..3 (8 floats)
    const int NC = Kdim / BK;

    const int wm = wid & 1;              // m half
    const int wn = wid >> 1;             // n quarter
    const int m_base = wm * 64;
    const int n_base = wn * 32;

    float acc[4][4][4];
#pragma unroll
    for (int i = 0; i < 4; i++)
#pragma unroll
        for (int j = 0; j < 4; j++)
#pragma unroll
            for (int k = 0; k < 4; k++) acc[i][j][k] = 0.f;

    // ldmatrix per-lane addressing pieces (constant)
    const int arow_in = lane & 15;
    const int asel = lane >> 4;          // 0/1 -> k chunk within kchunk
    const int brow_in = lane & 7;
    const int bsel = (lane >> 3) & 1;

    // ---- prologue: stage 0 ----
    {
        char* st = sm;
#pragma unroll
        for (int t = 0; t < 2; t++) {
            int r = r0g + t * 64;
            const float* p = arow + (size_t)r * Kdim + c0g * 8;
            float4 v0 = *reinterpret_cast<const float4*>(p);
            float4 v1 = *reinterpret_cast<const float4*>(p + 4);
            uint4 h, l;
            split8(v0, v1, h, l);
            uint32_t off = swz(r, c0g);
            *reinterpret_cast<uint4*>(st + AH_OFF + off) = h;
            *reinterpret_cast<uint4*>(st + AL_OFF + off) = l;
            const float* q = brow + (size_t)r * Kdim + c0g * 8;
            float4 w0 = *reinterpret_cast<const float4*>(q);
            float4 w1 = *reinterpret_cast<const float4*>(q + 4);
            split8(w0, w1, h, l);
            *reinterpret_cast<uint4*>(st + BH_OFF + off) = h;
            *reinterpret_cast<uint4*>(st + BL_OFF + off) = l;
        }
    }
    __syncthreads();

    for (int c = 0; c < NC; c++) {
        const uint32_t sbase = smb + (uint32_t)(c & 1) * STAGE_BYTES;
        char* nxt = sm + ((c + 1) & 1) * STAGE_BYTES;

        // prefetch next stage gmem -> regs
        float4 pa[2][2], pb[2][2];
        if (c + 1 < NC) {
            const float* ac = arow + (size_t)(c + 1) * BK;
            const float* bc = brow + (size_t)(c + 1) * BK;
#pragma unroll
            for (int t = 0; t < 2; t++) {
                int r = r0g + t * 64;
                const float* p = ac + (size_t)r * Kdim + c0g * 8;
                pa[t][0] = *reinterpret_cast<const float4*>(p);
                pa[t][1] = *reinterpret_cast<const float4*>(p + 4);
                const float* q = bc + (size_t)r * Kdim + c0g * 8;
                pb[t][0] = *reinterpret_cast<const float4*>(q);
                pb[t][1] = *reinterpret_cast<const float4*>(q + 4);
            }
        }

        // ---- compute k-chunk 0 ----
#pragma unroll
        for (int kc2 = 0; kc2 < 2; kc2++) {
            if (kc2 == 1 && c + 1 < NC) {
                // store next stage between the two k-chunks
#pragma unroll
                for (int t = 0; t < 2; t++) {
                    int r = r0g + t * 64;
                    uint4 h, l;
                    split8(pa[t][0], pa[t][1], h, l);
                    uint32_t off = swz(r, c0g);
                    *reinterpret_cast<uint4*>(nxt + AH_OFF + off) = h;
                    *reinterpret_cast<uint4*>(nxt + AL_OFF + off) = l;
                    split8(pb[t][0], pb[t][1], h, l);
                    *reinterpret_cast<uint4*>(nxt + BH_OFF + off) = h;
                    *reinterpret_cast<uint4*>(nxt + BL_OFF + off) = l;
                }
            }
            uint32_t ah[4][4], al[4][4], bh[4][2], bl[4][2];
            int achunk = kc2 * 2 + asel;
#pragma unroll
            for (int mi = 0; mi < 4; mi++) {
                uint32_t off = swz(m_base + mi * 16 + arow_in, achunk);
                ldsm4(ah[mi], sbase + AH_OFF + off);
                ldsm4(al[mi], sbase + AL_OFF + off);
            }
            int bchunk = kc2 * 2 + bsel;
#pragma unroll
            for (int ni = 0; ni < 4; ni++) {
                uint32_t off = swz(n_base + ni * 8 + brow_in, bchunk);
                ldsm2(bh[ni], sbase + BH_OFF + off);
                ldsm2(bl[ni], sbase + BL_OFF + off);
            }
#pragma unroll
            for (int mi = 0; mi < 4; mi++)
#pragma unroll
                for (int ni = 0; ni < 4; ni++) {
                    mma_bf16(acc[mi][ni], ah[mi], bh[ni]);
                    mma_bf16(acc[mi][ni], ah[mi], bl[ni]);
                    mma_bf16(acc[mi][ni], al[mi], bh[ni]);
                }
        }
        __syncthreads();
    }

    // ---- epilogue ----
    const int mrow0 = m0 + m_base;
    const int ncol0 = n0 + n_base;
#pragma unroll
    for (int mi = 0; mi < 4; mi++) {
#pragma unroll
        for (int half = 0; half < 2; half++) {
            int row = mrow0 + mi * 16 + (lane >> 2) + half * 8;
            float* crow = C + (size_t)row * N;
            const float* mrow = mask ? mask + (size_t)row * N : nullptr;
#pragma unroll
            for (int ni = 0; ni < 4; ni++) {
                int col = ncol0 + ni * 8 + (lane & 3) * 2;
                float v0 = acc[mi][ni][half * 2 + 0] * scale;
                float v1 = acc[mi][ni][half * 2 + 1] * scale;
                if (bias) {
                    v0 += bias[col];
                    v1 += bias[col + 1];
                }
                if (mrow) {
                    v0 += mrow[col];
                    v1 += mrow[col + 1];
                }
                *reinterpret_cast<float2*>(crow + col) = make_float2(v0, v1);
            }
        }
    }
}

// ---------------- batched transpose: V[b][2048][1024] -> Vt[b][1024][2048] --
__global__ __launch_bounds__(256) void transpose_kernel(
    const float* __restrict__ src, float* __restrict__ dst) {
    __shared__ float t[32][33];
    const float* s = src + (size_t)blockIdx.z * 2048 * 1024;
    float* d = dst + (size_t)blockIdx.z * 2048 * 1024;
    int c0 = blockIdx.x * 32;
    int r0 = blockIdx.y * 32;
    int tx = threadIdx.x & 31, ty = threadIdx.x >> 5;
#pragma unroll
    for (int i = 0; i < 32; i += 8)
        t[ty + i][tx] = s[(size_t)(r0 + ty + i) * 1024 + c0 + tx];
    __syncthreads();
#pragma unroll
    for (int i = 0; i < 32; i += 8)
        d[(size_t)(c0 + ty + i) * 2048 + r0 + tx] = t[tx][ty + i];
}

// ---------------- row softmax over 2048 cols ----------------
__global__ __launch_bounds__(256) void softmax_kernel(float* __restrict__ S,
                                                      int n) {
    size_t row = blockIdx.x;
    float* p = S + row * (size_t)n;
    int tid = threadIdx.x;
    int lane = tid & 31, warp = tid >> 5;

    float4 v0 = reinterpret_cast<float4*>(p)[tid];
    float4 v1 = reinterpret_cast<float4*>(p)[tid + 256];
    float v[8] = {v0.x, v0.y, v0.z, v0.w, v1.x, v1.y, v1.z, v1.w};
    __shared__ float red[8];

    float m = v[0];
#pragma unroll
    for (int j = 1; j < 8; j++) m = fmaxf(m, v[j]);
#pragma unroll
    for (int o = 16; o; o >>= 1) m = fmaxf(m, __shfl_xor_sync(0xffffffffu, m, o));
    if (lane == 0) red[warp] = m;
    __syncthreads();
    float mall = red[0];
#pragma unroll
    for (int i = 1; i < 8; i++) mall = fmaxf(mall, red[i]);
    __syncthreads();

    float s = 0.f;
#pragma unroll
    for (int j = 0; j < 8; j++) {
        v[j] = expf(v[j] - mall);
        s += v[j];
    }
#pragma unroll
    for (int o = 16; o; o >>= 1) s += __shfl_xor_sync(0xffffffffu, s, o);
    if (lane == 0) red[warp] = s;
    __syncthreads();
    float stot = 0.f;
#pragma unroll
    for (int i = 0; i < 8; i++) stot += red[i];
    float inv = 1.0f / stot;

    reinterpret_cast<float4*>(p)[tid] =
        make_float4(v[0] * inv, v[1] * inv, v[2] * inv, v[3] * inv);
    reinterpret_cast<float4*>(p)[tid + 256] =
        make_float4(v[4] * inv, v[5] * inv, v[6] * inv, v[7] * inv);
}

extern "C" void kernel_launch(void* const* d_in, const int* in_sizes, int n_in,
                              void* d_out, int out_size) {
    const float* x    = (const float*)d_in[0];
    const float* mask = (const float*)d_in[1];
    const float* w_q  = (const float*)d_in[2];
    const float* b_q  = (const float*)d_in[3];
    const float* w_k  = (const float*)d_in[4];
    const float* b_k  = (const float*)d_in[5];
    const float* w_v  = (const float*)d_in[6];
    const float* b_v  = (const float*)d_in[7];
    float* out = (float*)d_out;

    float *Qp, *Kp, *Vp, *Vtp, *Sp;
    cudaGetSymbolAddress((void**)&Qp, g_Q);
    cudaGetSymbolAddress((void**)&Kp, g_K);
    cudaGetSymbolAddress((void**)&Vp, g_V);
    cudaGetSymbolAddress((void**)&Vtp, g_Vt);
    cudaGetSymbolAddress((void**)&Sp, g_S);

    cudaFuncSetAttribute(gemm_mma, cudaFuncAttributeMaxDynamicSharedMemorySize,
                         SMEM_TOTAL);

    const int Bb = 4, Ss = 2048, Dd = 1024;
    const int M_qkv = Bb * Ss;  // 8192
    const float inv_sqrt_d = 1.0f / 32.0f;
    dim3 blk(256);

    // QKV projections: [8192,1024] = x @ W^T + b
    dim3 g_qkv(Dd / BN, M_qkv / BM, 1);
    gemm_mma<<<g_qkv, blk, SMEM_TOTAL>>>(x, w_q, Qp, M_qkv, Dd, Dd, 0, 0, 0,
                                         b_q, nullptr, 1.0f);
    gemm_mma<<<g_qkv, blk, SMEM_TOTAL>>>(x, w_k, Kp, M_qkv, Dd, Dd, 0, 0, 0,
                                         b_k, nullptr, 1.0f);
    gemm_mma<<<g_qkv, blk, SMEM_TOTAL>>>(x, w_v, Vp, M_qkv, Dd, Dd, 0, 0, 0,
                                         b_v, nullptr, 1.0f);

    // Vt[b] = V[b]^T  (so attn@V becomes NT)
    dim3 g_tr(Dd / 32, Ss / 32, Bb);
    transpose_kernel<<<g_tr, blk>>>(Vp, Vtp);

    // scores[b] = Q[b] @ K[b]^T / 32 + mask
    dim3 g_sc(Ss / BN, Ss / BM, Bb);
    gemm_mma<<<g_sc, blk, SMEM_TOTAL>>>(Qp, Kp, Sp, Ss, Ss, Dd,
                                        (long long)Ss * Dd, (long long)Ss * Dd,
                                        (long long)Ss * Ss, nullptr, mask,
                                        inv_sqrt_d);

    // softmax rows
    softmax_kernel<<<Bb * Ss, blk>>>(Sp, Ss);

    // out[b] = attn[b] @ Vt[b]^T
    dim3 g_av(Dd / BN, Ss / BM, Bb);
    gemm_mma<<<g_av, blk, SMEM_TOTAL>>>(Sp, Vtp, out, Ss, Dd, Ss,
                                        (long long)Ss * Ss, (long long)Ss * Dd,
                                        (long long)Ss * Dd, nullptr, nullptr,
                                        1.0f);
}

// round 12
// speedup vs baseline: 1.5659x; 1.5634x over previous
#include <cuda_runtime.h>
#include <cuda_fp16.h>
#include <math.h>
#include <stdint.h>

// ---------------------------------------------------------------------------
// SimpleSelfAttention B=4,S=2048,D=1024 fp32.
// All GEMMs via single fp16 mma.sync (m16n8k16, fp32 accum).
// fp16 rounding RMS ~2^-12.3 -> end-to-end rel_err ~3e-4 << 1e-3 gate.
// Intermediates (Q,K,V,Vt,attn) stored fp16: free error-wise (next GEMM
// rounds to fp16 anyway), halves memory traffic.
// ---------------------------------------------------------------------------

#define BM 128
#define BN 128
#define BK 32
#define A_OFF 0
#define B_OFF 8192
#define STAGE_BYTES 16384      // A(8K) + B(8K)
#define SMEM_TOTAL (2 * STAGE_BYTES)

// scratch (fp16 intermediates)
__device__ __half g_Qh[4 * 2048 * 1024];
__device__ __half g_Kh[4 * 2048 * 1024];
__device__ __half g_Vh[4 * 2048 * 1024];
__device__ __half g_Vt[4 * 2048 * 1024];
__device__ float  g_S [4 * 2048 * 2048];
__device__ __half g_Ah[4 * 2048 * 2048];

__device__ __forceinline__ uint32_t smem_u32(const void* p) {
    uint32_t a;
    asm("{ .reg .u64 t; cvta.to.shared.u64 t, %1; cvt.u32.u64 %0, t; }"
        : "=r"(a) : "l"(p));
    return a;
}

// Swizzled byte offset for (row, 16B-chunk) in a [rows][32 fp16] tile (64B rows).
// Conflict-free ldmatrix phases (validated in prior rounds).
__device__ __forceinline__ uint32_t swz(int r, int c) {
    return (uint32_t)(r * 64 + ((c ^ ((r >> 1) & 3)) << 4));
}

__device__ __forceinline__ void ldsm4(uint32_t* r, uint32_t a) {
    asm volatile(
        "ldmatrix.sync.aligned.m8n8.x4.shared.b16 {%0,%1,%2,%3}, [%4];"
        : "=r"(r[0]), "=r"(r[1]), "=r"(r[2]), "=r"(r[3]) : "r"(a));
}
__device__ __forceinline__ void ldsm2(uint32_t* r, uint32_t a) {
    asm volatile(
        "ldmatrix.sync.aligned.m8n8.x2.shared.b16 {%0,%1}, [%2];"
        : "=r"(r[0]), "=r"(r[1]) : "r"(a));
}
__device__ __forceinline__ void mma_f16(float* c, const uint32_t* a,
                                        const uint32_t* b) {
    asm volatile(
        "mma.sync.aligned.m16n8k16.row.col.f32.f16.f16.f32 "
        "{%0,%1,%2,%3}, {%4,%5,%6,%7}, {%8,%9}, {%0,%1,%2,%3};"
        : "+f"(c[0]), "+f"(c[1]), "+f"(c[2]), "+f"(c[3])
        : "r"(a[0]), "r"(a[1]), "r"(a[2]), "r"(a[3]), "r"(b[0]), "r"(b[1]));
}

__device__ __forceinline__ uint4 cvt8(const float4& a, const float4& b) {
    __half2 h0 = __floats2half2_rn(a.x, a.y);
    __half2 h1 = __floats2half2_rn(a.z, a.w);
    __half2 h2 = __floats2half2_rn(b.x, b.y);
    __half2 h3 = __floats2half2_rn(b.z, b.w);
    uint4 r;
    r.x = *reinterpret_cast<uint32_t*>(&h0);
    r.y = *reinterpret_cast<uint32_t*>(&h1);
    r.z = *reinterpret_cast<uint32_t*>(&h2);
    r.w = *reinterpret_cast<uint32_t*>(&h3);
    return r;
}

// load 8 contiguous elements as 8 fp16 (converting if fp32 source)
template <typename T>
__device__ __forceinline__ uint4 ld8(const T* p);
template <>
__device__ __forceinline__ uint4 ld8<float>(const float* p) {
    float4 a = *reinterpret_cast<const float4*>(p);
    float4 b = *reinterpret_cast<const float4*>(p + 4);
    return cvt8(a, b);
}
template <>
__device__ __forceinline__ uint4 ld8<__half>(const __half* p) {
    return *reinterpret_cast<const uint4*>(p);
}

__device__ __forceinline__ void st2(float* p, float a, float b) {
    *reinterpret_cast<float2*>(p) = make_float2(a, b);
}
__device__ __forceinline__ void st2(__half* p, float a, float b) {
    *reinterpret_cast<__half2*>(p) = __floats2half2_rn(a, b);
}

// ---------------- fp16 HMMA NT GEMM: C = scale*(A @ B^T) [+bias] [+mask] ---
template <typename TA, typename TB, typename TO>
__global__ __launch_bounds__(256, 1) void gemm_mma(
    const TA* __restrict__ Ag, const TB* __restrict__ Bg,
    TO* __restrict__ Cg, int N, int Kdim,
    long long sAz, long long sBz, long long sCz,
    const float* __restrict__ bias, const float* __restrict__ mask,
    float scale) {
    extern __shared__ char sm[];
    const uint32_t smb = smem_u32(sm);
    const int tid = threadIdx.x;
    const int wid = tid >> 5;
    const int lane = tid & 31;

    const TA* A = Ag + (long long)blockIdx.z * sAz;
    const TB* B = Bg + (long long)blockIdx.z * sBz;
    TO* C = Cg + (long long)blockIdx.z * sCz;
    const int m0 = blockIdx.y * BM;
    const int n0 = blockIdx.x * BN;

    const TA* arow = A + (size_t)m0 * Kdim;
    const TB* brow = B + (size_t)n0 * Kdim;

    const int r0g = tid >> 2;   // 0..63
    const int c0g = tid & 3;    // 16B chunk within 64B row
    const int NC = Kdim / BK;

    const int wm = wid & 1;
    const int wn = wid >> 1;
    const int m_base = wm * 64;
    const int n_base = wn * 32;

    float acc[4][4][4];
#pragma unroll
    for (int i = 0; i < 4; i++)
#pragma unroll
        for (int j = 0; j < 4; j++)
#pragma unroll
            for (int k = 0; k < 4; k++) acc[i][j][k] = 0.f;

    const int arow_in = lane & 15;
    const int asel = lane >> 4;
    const int brow_in = lane & 7;
    const int bsel = (lane >> 3) & 1;

    // ---- prologue: stage 0 ----
#pragma unroll
    for (int t = 0; t < 2; t++) {
        int r = r0g + t * 64;
        uint32_t off = swz(r, c0g);
        *reinterpret_cast<uint4*>(sm + A_OFF + off) =
            ld8(arow + (size_t)r * Kdim + c0g * 8);
        *reinterpret_cast<uint4*>(sm + B_OFF + off) =
            ld8(brow + (size_t)r * Kdim + c0g * 8);
    }
    __syncthreads();

    for (int c = 0; c < NC; c++) {
        const uint32_t sbase = smb + (uint32_t)(c & 1) * STAGE_BYTES;
        char* nxt = sm + ((c + 1) & 1) * STAGE_BYTES;

        uint4 qa[2], qb[2];
        if (c + 1 < NC) {
            const TA* ac = arow + (size_t)(c + 1) * BK;
            const TB* bc = brow + (size_t)(c + 1) * BK;
#pragma unroll
            for (int t = 0; t < 2; t++) {
                int r = r0g + t * 64;
                qa[t] = ld8(ac + (size_t)r * Kdim + c0g * 8);
                qb[t] = ld8(bc + (size_t)r * Kdim + c0g * 8);
            }
        }

#pragma unroll
        for (int kc2 = 0; kc2 < 2; kc2++) {
            if (kc2 == 1 && c + 1 < NC) {
#pragma unroll
                for (int t = 0; t < 2; t++) {
                    int r = r0g + t * 64;
                    uint32_t off = swz(r, c0g);
                    *reinterpret_cast<uint4*>(nxt + A_OFF + off) = qa[t];
                    *reinterpret_cast<uint4*>(nxt + B_OFF + off) = qb[t];
                }
            }
            uint32_t a[4][4], b[4][2];
            int achunk = kc2 * 2 + asel;
#pragma unroll
            for (int mi = 0; mi < 4; mi++)
                ldsm4(a[mi], sbase + A_OFF + swz(m_base + mi * 16 + arow_in, achunk));
            int bchunk = kc2 * 2 + bsel;
#pragma unroll
            for (int ni = 0; ni < 4; ni++)
                ldsm2(b[ni], sbase + B_OFF + swz(n_base + ni * 8 + brow_in, bchunk));
#pragma unroll
            for (int mi = 0; mi < 4; mi++)
#pragma unroll
                for (int ni = 0; ni < 4; ni++) mma_f16(acc[mi][ni], a[mi], b[ni]);
        }
        __syncthreads();
    }

    // ---- epilogue ----
    const int mrow0 = m0 + m_base;
    const int ncol0 = n0 + n_base;
#pragma unroll
    for (int mi = 0; mi < 4; mi++) {
#pragma unroll
        for (int hf = 0; hf < 2; hf++) {
            int row = mrow0 + mi * 16 + (lane >> 2) + hf * 8;
            TO* crow = C + (size_t)row * N;
            const float* mrow = mask ? mask + (size_t)row * N : nullptr;
#pragma unroll
            for (int ni = 0; ni < 4; ni++) {
                int col = ncol0 + ni * 8 + (lane & 3) * 2;
                float v0 = acc[mi][ni][hf * 2 + 0] * scale;
                float v1 = acc[mi][ni][hf * 2 + 1] * scale;
                if (bias) {
                    v0 += bias[col];
                    v1 += bias[col + 1];
                }
                if (mrow) {
                    v0 += mrow[col];
                    v1 += mrow[col + 1];
                }
                st2(crow + col, v0, v1);
            }
        }
    }
}

// ---------------- batched fp16 transpose: V[b][2048][1024] -> Vt[b][1024][2048]
__global__ __launch_bounds__(256) void transpose_h(
    const __half* __restrict__ src, __half* __restrict__ dst) {
    __shared__ __half t[32][33];
    const __half* s = src + (size_t)blockIdx.z * 2048 * 1024;
    __half* d = dst + (size_t)blockIdx.z * 2048 * 1024;
    int c0 = blockIdx.x * 32;   // col in src (D)
    int r0 = blockIdx.y * 32;   // row in src (S)
    int tx = threadIdx.x & 31, ty = threadIdx.x >> 5;
#pragma unroll
    for (int i = 0; i < 32; i += 8)
        t[ty + i][tx] = s[(size_t)(r0 + ty + i) * 1024 + c0 + tx];
    __syncthreads();
#pragma unroll
    for (int i = 0; i < 32; i += 8)
        d[(size_t)(c0 + ty + i) * 2048 + r0 + tx] = t[tx][ty + i];
}

// ---------------- row softmax: fp32 scores in, fp16 attn out ----------------
__global__ __launch_bounds__(256) void softmax_kernel(
    const float* __restrict__ S, __half* __restrict__ Ao, int n) {
    size_t row = blockIdx.x;
    const float* p = S + row * (size_t)n;
    __half* po = Ao + row * (size_t)n;
    int tid = threadIdx.x;
    int lane = tid & 31, warp = tid >> 5;

    float4 v0 = reinterpret_cast<const float4*>(p)[tid];
    float4 v1 = reinterpret_cast<const float4*>(p)[tid + 256];
    float v[8] = {v0.x, v0.y, v0.z, v0.w, v1.x, v1.y, v1.z, v1.w};
    __shared__ float red[8];

    float m = v[0];
#pragma unroll
    for (int j = 1; j < 8; j++) m = fmaxf(m, v[j]);
#pragma unroll
    for (int o = 16; o; o >>= 1) m = fmaxf(m, __shfl_xor_sync(0xffffffffu, m, o));
    if (lane == 0) red[warp] = m;
    __syncthreads();
    float mall = red[0];
#pragma unroll
    for (int i = 1; i < 8; i++) mall = fmaxf(mall, red[i]);
    __syncthreads();

    float s = 0.f;
#pragma unroll
    for (int j = 0; j < 8; j++) {
        v[j] = expf(v[j] - mall);
        s += v[j];
    }
#pragma unroll
    for (int o = 16; o; o >>= 1) s += __shfl_xor_sync(0xffffffffu, s, o);
    if (lane == 0) red[warp] = s;
    __syncthreads();
    float stot = 0.f;
#pragma unroll
    for (int i = 0; i < 8; i++) stot += red[i];
    float inv = 1.0f / stot;

    // cols [tid*4, tid*4+4) and [1024 + tid*4, ...)
    __half2 h0 = __floats2half2_rn(v[0] * inv, v[1] * inv);
    __half2 h1 = __floats2half2_rn(v[2] * inv, v[3] * inv);
    __half2 h2 = __floats2half2_rn(v[4] * inv, v[5] * inv);
    __half2 h3 = __floats2half2_rn(v[6] * inv, v[7] * inv);
    uint2 w0 = make_uint2(*reinterpret_cast<uint32_t*>(&h0),
                          *reinterpret_cast<uint32_t*>(&h1));
    uint2 w1 = make_uint2(*reinterpret_cast<uint32_t*>(&h2),
                          *reinterpret_cast<uint32_t*>(&h3));
    *reinterpret_cast<uint2*>(po + tid * 4) = w0;
    *reinterpret_cast<uint2*>(po + 1024 + tid * 4) = w1;
}

extern "C" void kernel_launch(void* const* d_in, const int* in_sizes, int n_in,
                              void* d_out, int out_size) {
    const float* x    = (const float*)d_in[0];
    const float* mask = (const float*)d_in[1];
    const float* w_q  = (const float*)d_in[2];
    const float* b_q  = (const float*)d_in[3];
    const float* w_k  = (const float*)d_in[4];
    const float* b_k  = (const float*)d_in[5];
    const float* w_v  = (const float*)d_in[6];
    const float* b_v  = (const float*)d_in[7];
    float* out = (float*)d_out;

    __half *Qh, *Kh, *Vh, *Vt, *Ah;
    float* Sp;
    cudaGetSymbolAddress((void**)&Qh, g_Qh);
    cudaGetSymbolAddress((void**)&Kh, g_Kh);
    cudaGetSymbolAddress((void**)&Vh, g_Vh);
    cudaGetSymbolAddress((void**)&Vt, g_Vt);
    cudaGetSymbolAddress((void**)&Sp, g_S);
    cudaGetSymbolAddress((void**)&Ah, g_Ah);

    const int Bb = 4, Ss = 2048, Dd = 1024;
    const int M_qkv = Bb * Ss;  // 8192
    const float inv_sqrt_d = 1.0f / 32.0f;
    dim3 blk(256);

    // QKV projections: fp32 in -> fp16 out
    dim3 g_qkv(Dd / BN, M_qkv / BM, 1);
    gemm_mma<float, float, __half><<<g_qkv, blk, SMEM_TOTAL>>>(
        x, w_q, Qh, Dd, Dd, 0, 0, 0, b_q, nullptr, 1.0f);
    gemm_mma<float, float, __half><<<g_qkv, blk, SMEM_TOTAL>>>(
        x, w_k, Kh, Dd, Dd, 0, 0, 0, b_k, nullptr, 1.0f);
    gemm_mma<float, float, __half><<<g_qkv, blk, SMEM_TOTAL>>>(
        x, w_v, Vh, Dd, Dd, 0, 0, 0, b_v, nullptr, 1.0f);

    // Vt[b] = V[b]^T (fp16)
    dim3 g_tr(Dd / 32, Ss / 32, Bb);
    transpose_h<<<g_tr, blk>>>(Vh, Vt);

    // scores[b] = Q[b] @ K[b]^T / 32 + mask  (fp16 in, fp32 out)
    dim3 g_sc(Ss / BN, Ss / BM, Bb);
    gemm_mma<__half, __half, float><<<g_sc, blk, SMEM_TOTAL>>>(
        Qh, Kh, Sp, Ss, Dd, (long long)Ss * Dd, (long long)Ss * Dd,
        (long long)Ss * Ss, nullptr, mask, inv_sqrt_d);

    // softmax rows -> fp16 attn
    softmax_kernel<<<Bb * Ss, blk>>>(Sp, Ah, Ss);

    // out[b] = attn[b] @ Vt[b]^T  (fp16 in, fp32 out)
    dim3 g_av(Dd / BN, Ss / BM, Bb);
    gemm_mma<__half, __half, float><<<g_av, blk, SMEM_TOTAL>>>(
        Ah, Vt, out, Dd, Ss, (long long)Ss * Ss, (long long)Ss * Dd,
        (long long)Ss * Dd, nullptr, nullptr, 1.0f);
}

// round 17
// speedup vs baseline: 1.5679x; 1.0012x over previous
#include <cuda_runtime.h>
#include <cuda_fp16.h>
#include <math.h>
#include <stdint.h>

// ---------------------------------------------------------------------------
// SimpleSelfAttention B=4,S=2048,D=1024 fp32.
// All GEMMs via single fp16 mma.sync (m16n8k16, fp32 accum).
// fp16 rounding RMS ~2^-12.3 -> end-to-end rel_err ~3e-4 << 1e-3 gate.
// Intermediates (Q,K,V,Vt,attn) stored fp16: free error-wise (next GEMM
// rounds to fp16 anyway), halves memory traffic.
// ---------------------------------------------------------------------------

#define BM 128
#define BN 128
#define BK 32
#define A_OFF 0
#define B_OFF 8192
#define STAGE_BYTES 16384      // A(8K) + B(8K)
#define SMEM_TOTAL (2 * STAGE_BYTES)

// scratch (fp16 intermediates)
__device__ __half g_Qh[4 * 2048 * 1024];
__device__ __half g_Kh[4 * 2048 * 1024];
__device__ __half g_Vh[4 * 2048 * 1024];
__device__ __half g_Vt[4 * 2048 * 1024];
__device__ float  g_S [4 * 2048 * 2048];
__device__ __half g_Ah[4 * 2048 * 2048];

__device__ __forceinline__ uint32_t smem_u32(const void* p) {
    uint32_t a;
    asm("{ .reg .u64 t; cvta.to.shared.u64 t, %1; cvt.u32.u64 %0, t; }"
        : "=r"(a) : "l"(p));
    return a;
}

// Swizzled byte offset for (row, 16B-chunk) in a [rows][32 fp16] tile (64B rows).
// Conflict-free ldmatrix phases (validated in prior rounds).
__device__ __forceinline__ uint32_t swz(int r, int c) {
    return (uint32_t)(r * 64 + ((c ^ ((r >> 1) & 3)) << 4));
}

__device__ __forceinline__ void ldsm4(uint32_t* r, uint32_t a) {
    asm volatile(
        "ldmatrix.sync.aligned.m8n8.x4.shared.b16 {%0,%1,%2,%3}, [%4];"
        : "=r"(r[0]), "=r"(r[1]), "=r"(r[2]), "=r"(r[3]) : "r"(a));
}
__device__ __forceinline__ void ldsm2(uint32_t* r, uint32_t a) {
    asm volatile(
        "ldmatrix.sync.aligned.m8n8.x2.shared.b16 {%0,%1}, [%2];"
        : "=r"(r[0]), "=r"(r[1]) : "r"(a));
}
__device__ __forceinline__ void mma_f16(float* c, const uint32_t* a,
                                        const uint32_t* b) {
    asm volatile(
        "mma.sync.aligned.m16n8k16.row.col.f32.f16.f16.f32 "
        "{%0,%1,%2,%3}, {%4,%5,%6,%7}, {%8,%9}, {%0,%1,%2,%3};"
        : "+f"(c[0]), "+f"(c[1]), "+f"(c[2]), "+f"(c[3])
        : "r"(a[0]), "r"(a[1]), "r"(a[2]), "r"(a[3]), "r"(b[0]), "r"(b[1]));
}

__device__ __forceinline__ uint4 cvt8(const float4& a, const float4& b) {
    __half2 h0 = __floats2half2_rn(a.x, a.y);
    __half2 h1 = __floats2half2_rn(a.z, a.w);
    __half2 h2 = __floats2half2_rn(b.x, b.y);
    __half2 h3 = __floats2half2_rn(b.z, b.w);
    uint4 r;
    r.x = *reinterpret_cast<uint32_t*>(&h0);
    r.y = *reinterpret_cast<uint32_t*>(&h1);
    r.z = *reinterpret_cast<uint32_t*>(&h2);
    r.w = *reinterpret_cast<uint32_t*>(&h3);
    return r;
}

// load 8 contiguous elements as 8 fp16 (converting if fp32 source)
template <typename T>
__device__ __forceinline__ uint4 ld8(const T* p);
template <>
__device__ __forceinline__ uint4 ld8<float>(const float* p) {
    float4 a = *reinterpret_cast<const float4*>(p);
    float4 b = *reinterpret_cast<const float4*>(p + 4);
    return cvt8(a, b);
}
template <>
__device__ __forceinline__ uint4 ld8<__half>(const __half* p) {
    return *reinterpret_cast<const uint4*>(p);
}

__device__ __forceinline__ void st2(float* p, float a, float b) {
    *reinterpret_cast<float2*>(p) = make_float2(a, b);
}
__device__ __forceinline__ void st2(__half* p, float a, float b) {
    *reinterpret_cast<__half2*>(p) = __floats2half2_rn(a, b);
}

// ---------------- fp16 HMMA NT GEMM: C = scale*(A @ B^T) [+bias] [+mask] ---
template <typename TA, typename TB, typename TO>
__global__ __launch_bounds__(256, 1) void gemm_mma(
    const TA* __restrict__ Ag, const TB* __restrict__ Bg,
    TO* __restrict__ Cg, int N, int Kdim,
    long long sAz, long long sBz, long long sCz,
    const float* __restrict__ bias, const float* __restrict__ mask,
    float scale) {
    extern __shared__ char sm[];
    const uint32_t smb = smem_u32(sm);
    const int tid = threadIdx.x;
    const int wid = tid >> 5;
    const int lane = tid & 31;

    const TA* A = Ag + (long long)blockIdx.z * sAz;
    const TB* B = Bg + (long long)blockIdx.z * sBz;
    TO* C = Cg + (long long)blockIdx.z * sCz;
    const int m0 = blockIdx.y * BM;
    const int n0 = blockIdx.x * BN;

    const TA* arow = A + (size_t)m0 * Kdim;
    const TB* brow = B + (size_t)n0 * Kdim;

    const int r0g = tid >> 2;   // 0..63
    const int c0g = tid & 3;    // 16B chunk within 64B row
    const int NC = Kdim / BK;

    const int wm = wid & 1;
    const int wn = wid >> 1;
    const int m_base = wm * 64;
    const int n_base = wn * 32;

    float acc[4][4][4];
#pragma unroll
    for (int i = 0; i < 4; i++)
#pragma unroll
        for (int j = 0; j < 4; j++)
#pragma unroll
            for (int k = 0; k < 4; k++) acc[i][j][k] = 0.f;

    const int arow_in = lane & 15;
    const int asel = lane >> 4;
    const int brow_in = lane & 7;
    const int bsel = (lane >> 3) & 1;

    // ---- prologue: stage 0 ----
#pragma unroll
    for (int t = 0; t < 2; t++) {
        int r = r0g + t * 64;
        uint32_t off = swz(r, c0g);
        *reinterpret_cast<uint4*>(sm + A_OFF + off) =
            ld8(arow + (size_t)r * Kdim + c0g * 8);
        *reinterpret_cast<uint4*>(sm + B_OFF + off) =
            ld8(brow + (size_t)r * Kdim + c0g * 8);
    }
    __syncthreads();

    for (int c = 0; c < NC; c++) {
        const uint32_t sbase = smb + (uint32_t)(c & 1) * STAGE_BYTES;
        char* nxt = sm + ((c + 1) & 1) * STAGE_BYTES;

        uint4 qa[2], qb[2];
        if (c + 1 < NC) {
            const TA* ac = arow + (size_t)(c + 1) * BK;
            const TB* bc = brow + (size_t)(c + 1) * BK;
#pragma unroll
            for (int t = 0; t < 2; t++) {
                int r = r0g + t * 64;
                qa[t] = ld8(ac + (size_t)r * Kdim + c0g * 8);
                qb[t] = ld8(bc + (size_t)r * Kdim + c0g * 8);
            }
        }

#pragma unroll
        for (int kc2 = 0; kc2 < 2; kc2++) {
            if (kc2 == 1 && c + 1 < NC) {
#pragma unroll
                for (int t = 0; t < 2; t++) {
                    int r = r0g + t * 64;
                    uint32_t off = swz(r, c0g);
                    *reinterpret_cast<uint4*>(nxt + A_OFF + off) = qa[t];
                    *reinterpret_cast<uint4*>(nxt + B_OFF + off) = qb[t];
                }
            }
            uint32_t a[4][4], b[4][2];
            int achunk = kc2 * 2 + asel;
#pragma unroll
            for (int mi = 0; mi < 4; mi++)
                ldsm4(a[mi], sbase + A_OFF + swz(m_base + mi * 16 + arow_in, achunk));
            int bchunk = kc2 * 2 + bsel;
#pragma unroll
            for (int ni = 0; ni < 4; ni++)
                ldsm2(b[ni], sbase + B_OFF + swz(n_base + ni * 8 + brow_in, bchunk));
#pragma unroll
            for (int mi = 0; mi < 4; mi++)
#pragma unroll
                for (int ni = 0; ni < 4; ni++) mma_f16(acc[mi][ni], a[mi], b[ni]);
        }
        __syncthreads();
    }

    // ---- epilogue ----
    const int mrow0 = m0 + m_base;
    const int ncol0 = n0 + n_base;
#pragma unroll
    for (int mi = 0; mi < 4; mi++) {
#pragma unroll
        for (int hf = 0; hf < 2; hf++) {
            int row = mrow0 + mi * 16 + (lane >> 2) + hf * 8;
            TO* crow = C + (size_t)row * N;
            const float* mrow = mask ? mask + (size_t)row * N : nullptr;
#pragma unroll
            for (int ni = 0; ni < 4; ni++) {
                int col = ncol0 + ni * 8 + (lane & 3) * 2;
                float v0 = acc[mi][ni][hf * 2 + 0] * scale;
                float v1 = acc[mi][ni][hf * 2 + 1] * scale;
                if (bias) {
                    v0 += bias[col];
                    v1 += bias[col + 1];
                }
                if (mrow) {
                    v0 += mrow[col];
                    v1 += mrow[col + 1];
                }
                st2(crow + col, v0, v1);
            }
        }
    }
}

// ---------------- batched fp16 transpose: V[b][2048][1024] -> Vt[b][1024][2048]
__global__ __launch_bounds__(256) void transpose_h(
    const __half* __restrict__ src, __half* __restrict__ dst) {
    __shared__ __half t[32][33];
    const __half* s = src + (size_t)blockIdx.z * 2048 * 1024;
    __half* d = dst + (size_t)blockIdx.z * 2048 * 1024;
    int c0 = blockIdx.x * 32;   // col in src (D)
    int r0 = blockIdx.y * 32;   // row in src (S)
    int tx = threadIdx.x & 31, ty = threadIdx.x >> 5;
#pragma unroll
    for (int i = 0; i < 32; i += 8)
        t[ty + i][tx] = s[(size_t)(r0 + ty + i) * 1024 + c0 + tx];
    __syncthreads();
#pragma unroll
    for (int i = 0; i < 32; i += 8)
        d[(size_t)(c0 + ty + i) * 2048 + r0 + tx] = t[tx][ty + i];
}

// ---------------- row softmax: fp32 scores in, fp16 attn out ----------------
__global__ __launch_bounds__(256) void softmax_kernel(
    const float* __restrict__ S, __half* __restrict__ Ao, int n) {
    size_t row = blockIdx.x;
    const float* p = S + row * (size_t)n;
    __half* po = Ao + row * (size_t)n;
    int tid = threadIdx.x;
    int lane = tid & 31, warp = tid >> 5;

    float4 v0 = reinterpret_cast<const float4*>(p)[tid];
    float4 v1 = reinterpret_cast<const float4*>(p)[tid + 256];
    float v[8] = {v0.x, v0.y, v0.z, v0.w, v1.x, v1.y, v1.z, v1.w};
    __shared__ float red[8];

    float m = v[0];
#pragma unroll
    for (int j = 1; j < 8; j++) m = fmaxf(m, v[j]);
#pragma unroll
    for (int o = 16; o; o >>= 1) m = fmaxf(m, __shfl_xor_sync(0xffffffffu, m, o));
    if (lane == 0) red[warp] = m;
    __syncthreads();
    float mall = red[0];
#pragma unroll
    for (int i = 1; i < 8; i++) mall = fmaxf(mall, red[i]);
    __syncthreads();

    float s = 0.f;
#pragma unroll
    for (int j = 0; j < 8; j++) {
        v[j] = expf(v[j] - mall);
        s += v[j];
    }
#pragma unroll
    for (int o = 16; o; o >>= 1) s += __shfl_xor_sync(0xffffffffu, s, o);
    if (lane == 0) red[warp] = s;
    __syncthreads();
    float stot = 0.f;
#pragma unroll
    for (int i = 0; i < 8; i++) stot += red[i];
    float inv = 1.0f / stot;

    // cols [tid*4, tid*4+4) and [1024 + tid*4, ...)
    __half2 h0 = __floats2half2_rn(v[0] * inv, v[1] * inv);
    __half2 h1 = __floats2half2_rn(v[2] * inv, v[3] * inv);
    __half2 h2 = __floats2half2_rn(v[4] * inv, v[5] * inv);
    __half2 h3 = __floats2half2_rn(v[6] * inv, v[7] * inv);
    uint2 w0 = make_uint2(*reinterpret_cast<uint32_t*>(&h0),
                          *reinterpret_cast<uint32_t*>(&h1));
    uint2 w1 = make_uint2(*reinterpret_cast<uint32_t*>(&h2),
                          *reinterpret_cast<uint32_t*>(&h3));
    *reinterpret_cast<uint2*>(po + tid * 4) = w0;
    *reinterpret_cast<uint2*>(po + 1024 + tid * 4) = w1;
}

extern "C" void kernel_launch(void* const* d_in, const int* in_sizes, int n_in,
                              void* d_out, int out_size) {
    const float* x    = (const float*)d_in[0];
    const float* mask = (const float*)d_in[1];
    const float* w_q  = (const float*)d_in[2];
    const float* b_q  = (const float*)d_in[3];
    const float* w_k  = (const float*)d_in[4];
    const float* b_k  = (const float*)d_in[5];
    const float* w_v  = (const float*)d_in[6];
    const float* b_v  = (const float*)d_in[7];
    float* out = (float*)d_out;

    __half *Qh, *Kh, *Vh, *Vt, *Ah;
    float* Sp;
    cudaGetSymbolAddress((void**)&Qh, g_Qh);
    cudaGetSymbolAddress((void**)&Kh, g_Kh);
    cudaGetSymbolAddress((void**)&Vh, g_Vh);
    cudaGetSymbolAddress((void**)&Vt, g_Vt);
    cudaGetSymbolAddress((void**)&Sp, g_S);
    cudaGetSymbolAddress((void**)&Ah, g_Ah);

    const int Bb = 4, Ss = 2048, Dd = 1024;
    const int M_qkv = Bb * Ss;  // 8192
    const float inv_sqrt_d = 1.0f / 32.0f;
    dim3 blk(256);

    // QKV projections: fp32 in -> fp16 out
    dim3 g_qkv(Dd / BN, M_qkv / BM, 1);
    gemm_mma<float, float, __half><<<g_qkv, blk, SMEM_TOTAL>>>(
        x, w_q, Qh, Dd, Dd, 0, 0, 0, b_q, nullptr, 1.0f);
    gemm_mma<float, float, __half><<<g_qkv, blk, SMEM_TOTAL>>>(
        x, w_k, Kh, Dd, Dd, 0, 0, 0, b_k, nullptr, 1.0f);
    gemm_mma<float, float, __half><<<g_qkv, blk, SMEM_TOTAL>>>(
        x, w_v, Vh, Dd, Dd, 0, 0, 0, b_v, nullptr, 1.0f);

    // Vt[b] = V[b]^T (fp16)
    dim3 g_tr(Dd / 32, Ss / 32, Bb);
    transpose_h<<<g_tr, blk>>>(Vh, Vt);

    // scores[b] = Q[b] @ K[b]^T / 32 + mask  (fp16 in, fp32 out)
    dim3 g_sc(Ss / BN, Ss / BM, Bb);
    gemm_mma<__half, __half, float><<<g_sc, blk, SMEM_TOTAL>>>(
        Qh, Kh, Sp, Ss, Dd, (long long)Ss * Dd, (long long)Ss * Dd,
        (long long)Ss * Ss, nullptr, mask, inv_sqrt_d);

    // softmax rows -> fp16 attn
    softmax_kernel<<<Bb * Ss, blk>>>(Sp, Ah, Ss);

    // out[b] = attn[b] @ Vt[b]^T  (fp16 in, fp32 out)
    dim3 g_av(Dd / BN, Ss / BM, Bb);
    gemm_mma<__half, __half, float><<<g_av, blk, SMEM_TOTAL>>>(
        Ah, Vt, out, Dd, Ss, (long long)Ss * Ss, (long long)Ss * Dd,
        (long long)Ss * Dd, nullptr, nullptr, 1.0f);
}